// round 1
// baseline (speedup 1.0000x reference)
#include <cuda_runtime.h>
#include <math.h>

#define Bq 4
#define Lq 6
#define Qq 900
#define Cq 256
#define Nq (Lq*Qq)          /* 5400 */
#define NT ((Nq+63)/64)     /* 85 tiles */
#define DUP_THR 0.8f

// ---------------- scratch (device globals; no allocation allowed) ----------------
__device__ float               g_normSig[(size_t)Bq*Nq*Cq];  // compacted normalized selected rows
__device__ int                 g_selList[Bq*Nq];             // compact m -> node index
__device__ int                 g_parent[Bq*Nq];              // union-find parents (per image)
__device__ unsigned long long  g_best[Bq*Nq];                // per-root packed (score, ~idx)
__device__ unsigned char       g_sel[Bq*Nq];                 // effective selection flag
__device__ float               g_score[Bq*Nq];               // sigmoid scores
__device__ int                 g_slotNode[Bq*Nq];            // output slot -> seed node
__device__ int                 g_cnt[Bq];                    // raw threshold count
__device__ int                 g_selCount[Bq];               // compact count M
__device__ int                 g_seedCount[Bq];              // #components K
__device__ unsigned long long  g_argmax[Bq];                 // packed argmax for fallback

// ---------------- union-find ----------------
__device__ __forceinline__ int uf_find(int* parent, int x){
    while (true){
        int p = parent[x];
        if (p == x) return x;
        int gp = parent[p];
        if (gp != p){ parent[x] = gp; x = gp; }
        else return p;
    }
}
__device__ __forceinline__ void uf_union(int* parent, int a, int b){
    while (true){
        a = uf_find(parent, a);
        b = uf_find(parent, b);
        if (a == b) return;
        if (a > b){ int t=a; a=b; b=t; }          // hook larger root under smaller -> root = min idx
        if (atomicCAS(&parent[b], b, a) == b) return;
    }
}

// ---------------- kernels ----------------
__global__ void k0_zero(){
    int t = threadIdx.x;
    if (t < Bq){ g_cnt[t]=0; g_selCount[t]=0; g_seedCount[t]=0; g_argmax[t]=0ULL; }
}

__global__ void k1_init(const float* __restrict__ logits){
    int idx = blockIdx.x*256 + threadIdx.x;
    if (idx >= Bq*Nq) return;
    int b = idx / Nq, n = idx % Nq;
    int l = n / Qq, q = n % Qq;
    float lg = logits[(l*Bq + b)*Qq + q];               // [L,B,Q] -> per-image n = l*Q+q
    float sc = 1.0f/(1.0f + expf(-lg));
    bool sel = (lg >= 0.0f);                            // sigmoid(x)>=0.5 <=> x>=0
    g_score[idx] = sc;
    g_sel[idx]   = sel ? 1 : 0;
    g_parent[idx]= n;
    g_best[idx]  = 0ULL;
    if (sel) atomicAdd(&g_cnt[b], 1);
    unsigned long long key = ((unsigned long long)__float_as_uint(sc) << 32)
                           | (unsigned long long)(0xFFFFFFFFu - (unsigned)n);
    atomicMax(&g_argmax[b], key);                       // max score, tie -> smallest n
}

// one block (256 thr) per node: effective selection, compaction, L2-normalize row
__global__ void k2_normalize(const float* __restrict__ qs){
    int row = blockIdx.x;                 // 0..B*N-1
    int b = row / Nq, n = row % Nq;
    int t = threadIdx.x;                  // 256 == C
    __shared__ float red[8];
    __shared__ int   sm_m;
    bool selEff;
    if (g_cnt[b] > 0) selEff = (g_sel[row] != 0);
    else {
        unsigned am = 0xFFFFFFFFu - (unsigned)(g_argmax[b] & 0xFFFFFFFFull);
        selEff = ((unsigned)n == am);     // fallback: argmax only
    }
    if (t == 0){
        g_sel[row] = selEff ? 1 : 0;
        if (selEff){
            int m = atomicAdd(&g_selCount[b], 1);
            sm_m = m;
            g_selList[b*Nq + m] = n;
        }
    }
    __syncthreads();
    if (!selEff) return;                  // uniform across block
    int l = n / Qq, q = n % Qq;
    const float* src = qs + (((size_t)l*Bq + b)*Qq + q)*Cq;
    float v = src[t];
    float s = v*v;
    #pragma unroll
    for (int o=16;o>0;o>>=1) s += __shfl_down_sync(0xFFFFFFFFu, s, o);
    if ((t & 31) == 0) red[t >> 5] = s;
    __syncthreads();
    if (t == 0){
        float tot = 0.f;
        #pragma unroll
        for (int i=0;i<8;i++) tot += red[i];
        red[0] = rsqrtf(tot + 1e-12f);
    }
    __syncthreads();
    g_normSig[((size_t)b*Nq + sm_m)*Cq + t] = v * red[0];
}

// pairwise cosine sim on compacted selected rows; union pairs above threshold
__global__ void k3_sim(){
    int b  = blockIdx.z;
    int bx = blockIdx.x, by = blockIdx.y;
    if (by > bx) return;                  // upper triangle of tiles (incl. diagonal)
    int M = g_selCount[b];
    int r0 = by*64, c0 = bx*64;
    if (r0 >= M || c0 >= M) return;
    __shared__ float As[64][33];
    __shared__ float Bs[64][33];
    const float* base = g_normSig + (size_t)b*Nq*Cq;
    int tid = threadIdx.x;                // 256
    int tx = tid & 15, ty = tid >> 4;
    float acc[4][4];
    #pragma unroll
    for (int i=0;i<4;i++)
        #pragma unroll
        for (int j=0;j<4;j++) acc[i][j] = 0.f;

    for (int k0=0; k0<Cq; k0+=32){
        #pragma unroll
        for (int it=0; it<2; it++){
            int e   = tid + it*256;       // 0..511
            int rr  = e >> 3;             // row within tile
            int cc4 = e & 7;              // float4 column
            float4 va = make_float4(0,0,0,0), vb = va;
            int ga = r0 + rr, gb = c0 + rr;
            if (ga < M) va = *(const float4*)(base + (size_t)ga*Cq + k0 + cc4*4);
            if (gb < M) vb = *(const float4*)(base + (size_t)gb*Cq + k0 + cc4*4);
            As[rr][cc4*4+0]=va.x; As[rr][cc4*4+1]=va.y; As[rr][cc4*4+2]=va.z; As[rr][cc4*4+3]=va.w;
            Bs[rr][cc4*4+0]=vb.x; Bs[rr][cc4*4+1]=vb.y; Bs[rr][cc4*4+2]=vb.z; Bs[rr][cc4*4+3]=vb.w;
        }
        __syncthreads();
        #pragma unroll 8
        for (int k=0;k<32;k++){
            float a[4], bb[4];
            #pragma unroll
            for (int i=0;i<4;i++) a[i]  = As[ty*4+i][k];
            #pragma unroll
            for (int j=0;j<4;j++) bb[j] = Bs[tx*4+j][k];
            #pragma unroll
            for (int i=0;i<4;i++)
                #pragma unroll
                for (int j=0;j<4;j++) acc[i][j] = fmaf(a[i], bb[j], acc[i][j]);
        }
        __syncthreads();
    }
    int* par = g_parent + b*Nq;
    #pragma unroll
    for (int i=0;i<4;i++)
        #pragma unroll
        for (int j=0;j<4;j++){
            int mi = r0 + ty*4 + i, mj = c0 + tx*4 + j;
            if (mi < M && mj < M && acc[i][j] >= DUP_THR){
                int ni = g_selList[b*Nq+mi], nj = g_selList[b*Nq+mj];
                if (ni != nj) uf_union(par, ni, nj);
            }
        }
}

// flatten parents + per-component best (max score, tie smallest index)
__global__ void k4_flatten(){
    int idx = blockIdx.x*256 + threadIdx.x;
    if (idx >= Bq*Nq) return;
    int b = idx / Nq, n = idx % Nq;
    int* par = g_parent + b*Nq;
    int r = uf_find(par, n);
    par[n] = r;
    if (g_sel[idx]){
        unsigned long long key = ((unsigned long long)__float_as_uint(g_score[idx]) << 32)
                               | (unsigned long long)(0xFFFFFFFFu - (unsigned)n);
        atomicMax(&g_best[b*Nq + r], key);
    }
}

// per-image exclusive scan over roots (ascending node idx == ascending component root)
__global__ void k5_scan(){
    int b = blockIdx.x;
    int t = threadIdx.x;                  // 1024
    const int IPT = (Nq + 1023)/1024;     // 6
    int base = t*IPT;
    int flags[IPT];
    int s = 0;
    #pragma unroll
    for (int i=0;i<IPT;i++){
        int n = base + i; int f = 0;
        if (n < Nq && g_sel[b*Nq+n] && g_parent[b*Nq+n] == n) f = 1;
        flags[i] = f; s += f;
    }
    int lane = t & 31, wid = t >> 5;
    int v = s;
    #pragma unroll
    for (int o=1;o<32;o<<=1){ int u=__shfl_up_sync(0xFFFFFFFFu,v,o); if(lane>=o) v+=u; }
    __shared__ int wsum[32];
    if (lane == 31) wsum[wid] = v;
    __syncthreads();
    if (wid == 0){
        int w = wsum[lane];
        #pragma unroll
        for (int o=1;o<32;o<<=1){ int u=__shfl_up_sync(0xFFFFFFFFu,w,o); if(lane>=o) w+=u; }
        wsum[lane] = w;
    }
    __syncthreads();
    int excl = v - s + (wid > 0 ? wsum[wid-1] : 0);
    if (t == 0) g_seedCount[b] = wsum[31];
    int p = excl;
    #pragma unroll
    for (int i=0;i<IPT;i++){
        if (flags[i]){
            int n = base + i;
            unsigned long long bk = g_best[b*Nq + n];
            int node = (int)(0xFFFFFFFFu - (unsigned)(bk & 0xFFFFFFFFull));
            g_slotNode[b*Nq + p] = node;
            p++;
        }
    }
}

// seed_signatures: [B, N, C] (zeros beyond K; d_out is poisoned so write everything)
__global__ void k6_outsig(const float* __restrict__ qs, float* __restrict__ out){
    int row = blockIdx.x;                 // B*N blocks
    int b = row / Nq, slot = row % Nq;
    float v = 0.0f;
    if (slot < g_seedCount[b]){
        int node = g_slotNode[b*Nq + slot];
        int l = node / Qq, q = node % Qq;
        v = qs[(((size_t)l*Bq + b)*Qq + q)*Cq + threadIdx.x];
    }
    out[(size_t)row*Cq + threadIdx.x] = v;
}

// pad_mask [B,N] then seed_scores [B,N]
__global__ void k7_outsmall(float* __restrict__ out){
    int idx = blockIdx.x*256 + threadIdx.x;
    if (idx >= Bq*Nq) return;
    int b = idx / Nq, slot = idx % Nq;
    float m = 0.f, sc = 0.f;
    if (slot < g_seedCount[b]){
        m = 1.0f;
        sc = g_score[b*Nq + g_slotNode[b*Nq + slot]];
    }
    float* maskOut  = out + (size_t)Bq*Nq*Cq;
    float* scoreOut = maskOut + Bq*Nq;
    maskOut[idx]  = m;
    scoreOut[idx] = sc;
}

// ---------------- launch ----------------
extern "C" void kernel_launch(void* const* d_in, const int* in_sizes, int n_in,
                              void* d_out, int out_size){
    const float* qs     = (const float*)d_in[0];  // [L,B,Q,C]
    const float* logits = (const float*)d_in[1];  // [L,B,Q]
    float* out = (float*)d_out;
    (void)in_sizes; (void)n_in; (void)out_size;

    k0_zero<<<1, 32>>>();
    k1_init<<<(Bq*Nq + 255)/256, 256>>>(logits);
    k2_normalize<<<Bq*Nq, 256>>>(qs);
    dim3 g3(NT, NT, Bq);
    k3_sim<<<g3, 256>>>();
    k4_flatten<<<(Bq*Nq + 255)/256, 256>>>();
    k5_scan<<<Bq, 1024>>>();
    k6_outsig<<<Bq*Nq, 256>>>(qs, out);
    k7_outsmall<<<(Bq*Nq + 255)/256, 256>>>(out);
}

// round 2
// speedup vs baseline: 3.4647x; 3.4647x over previous
#include <cuda_runtime.h>
#include <cuda_bf16.h>
#include <math.h>

#define Bq 4
#define Lq 6
#define Qq 900
#define Cq 256
#define Nq (Lq*Qq)          /* 5400 */
#define BM 64
#define NT ((Nq+BM-1)/BM)   /* 85 tiles */
#define BK 64
#define BKP 72              /* padded row length (bf16 elems) */
#define DUP_THR 0.8f

// ---------------- scratch (device globals) ----------------
__device__ __nv_bfloat16       g_normBf[(size_t)Bq*Nq*Cq];   // compacted normalized rows (bf16)
__device__ int                 g_selList[Bq*Nq];             // compact m -> node index
__device__ int                 g_parent[Bq*Nq];              // union-find parents
__device__ unsigned long long  g_best[Bq*Nq];                // per-root packed (score, ~idx)
__device__ unsigned char       g_sel[Bq*Nq];                 // effective selection flag
__device__ float               g_score[Bq*Nq];               // sigmoid scores
__device__ int                 g_slotNode[Bq*Nq];            // output slot -> seed node
__device__ int                 g_cnt[Bq];
__device__ int                 g_selCount[Bq];
__device__ int                 g_seedCount[Bq];
__device__ unsigned long long  g_argmax[Bq];

// ---------------- union-find ----------------
__device__ __forceinline__ int uf_find(int* parent, int x){
    while (true){
        int p = parent[x];
        if (p == x) return x;
        int gp = parent[p];
        if (gp != p){ parent[x] = gp; x = gp; }
        else return p;
    }
}
__device__ __forceinline__ void uf_union(int* parent, int a, int b){
    while (true){
        a = uf_find(parent, a);
        b = uf_find(parent, b);
        if (a == b) return;
        if (a > b){ int t=a; a=b; b=t; }
        if (atomicCAS(&parent[b], b, a) == b) return;
    }
}

// ---------------- kernels ----------------
__global__ void k0_zero(){
    int t = threadIdx.x;
    if (t < Bq){ g_cnt[t]=0; g_selCount[t]=0; g_seedCount[t]=0; g_argmax[t]=0ULL; }
}

__global__ void k1_init(const float* __restrict__ logits){
    int idx = blockIdx.x*256 + threadIdx.x;
    if (idx >= Bq*Nq) return;
    int b = idx / Nq, n = idx % Nq;
    int l = n / Qq, q = n % Qq;
    float lg = logits[(l*Bq + b)*Qq + q];
    float sc = 1.0f/(1.0f + expf(-lg));
    bool sel = (lg >= 0.0f);
    g_score[idx] = sc;
    g_sel[idx]   = sel ? 1 : 0;
    g_parent[idx]= n;
    g_best[idx]  = 0ULL;
    if (sel) atomicAdd(&g_cnt[b], 1);
    unsigned long long key = ((unsigned long long)__float_as_uint(sc) << 32)
                           | (unsigned long long)(0xFFFFFFFFu - (unsigned)n);
    atomicMax(&g_argmax[b], key);
}

// one block (256 thr == C) per node: selection, compaction, L2-normalize row -> bf16
__global__ void k2_normalize(const float* __restrict__ qs){
    int row = blockIdx.x;                 // 0..B*N-1
    int b = row / Nq, n = row % Nq;
    int t = threadIdx.x;
    __shared__ float red[8];
    __shared__ int   sm_m;
    bool selEff;
    if (g_cnt[b] > 0) selEff = (g_sel[row] != 0);
    else {
        unsigned am = 0xFFFFFFFFu - (unsigned)(g_argmax[b] & 0xFFFFFFFFull);
        selEff = ((unsigned)n == am);
    }
    if (t == 0){
        g_sel[row] = selEff ? 1 : 0;
        if (selEff){
            int m = atomicAdd(&g_selCount[b], 1);
            sm_m = m;
            g_selList[b*Nq + m] = n;
        }
    }
    __syncthreads();
    if (!selEff) return;
    int l = n / Qq, q = n % Qq;
    const float* src = qs + (((size_t)l*Bq + b)*Qq + q)*Cq;
    float v = src[t];
    float s = v*v;
    #pragma unroll
    for (int o=16;o>0;o>>=1) s += __shfl_down_sync(0xFFFFFFFFu, s, o);
    if ((t & 31) == 0) red[t >> 5] = s;
    __syncthreads();
    if (t == 0){
        float tot = 0.f;
        #pragma unroll
        for (int i=0;i<8;i++) tot += red[i];
        red[0] = rsqrtf(tot + 1e-12f);
    }
    __syncthreads();
    g_normBf[((size_t)b*Nq + sm_m)*Cq + t] = __float2bfloat16_rn(v * red[0]);
}

// bf16 tensor-core pairwise sim; union pairs >= threshold.
// Block: 128 threads (4 warps, 2x2 warp grid, each warp 32x32 via m16n8k16).
__global__ void __launch_bounds__(128, 8) k3_sim(){
    int b  = blockIdx.z;
    int bx = blockIdx.x, by = blockIdx.y;
    if (by > bx) return;                  // upper triangle of tiles
    int M = g_selCount[b];
    int r0 = by*BM, c0 = bx*BM;
    if (r0 >= M || c0 >= M) return;

    __shared__ __nv_bfloat16 As[BM][BKP];
    __shared__ __nv_bfloat16 Bs[BM][BKP];

    const __nv_bfloat16* base = g_normBf + (size_t)b*Nq*Cq;
    int tid  = threadIdx.x;
    int lane = tid & 31;
    int w    = tid >> 5;                  // 0..3
    int wm   = w >> 1, wn = w & 1;        // warp coords (2x2)
    int g    = lane >> 2;                 // group 0..7
    int tig  = lane & 3;                  // thread-in-group

    float acc[2][4][4];                   // [m-tile][n-tile][c regs]
    #pragma unroll
    for (int i=0;i<2;i++)
        #pragma unroll
        for (int j=0;j<4;j++)
            #pragma unroll
            for (int c=0;c<4;c++) acc[i][j][c] = 0.f;

    for (int k0=0; k0<Cq; k0+=BK){
        // load A/B tiles: 64 rows x 64 bf16 each = 512 uint4 per tile
        #pragma unroll
        for (int it=0; it<4; it++){
            int e   = tid + it*128;       // 0..511
            int rr  = e >> 3;
            int col = (e & 7)*8;          // bf16 col
            uint4 va = make_uint4(0,0,0,0), vb = va;
            int ga = r0 + rr, gb = c0 + rr;
            if (ga < M) va = *(const uint4*)(base + (size_t)ga*Cq + k0 + col);
            if (gb < M) vb = *(const uint4*)(base + (size_t)gb*Cq + k0 + col);
            *(uint4*)(&As[rr][col]) = va;
            *(uint4*)(&Bs[rr][col]) = vb;
        }
        __syncthreads();

        #pragma unroll
        for (int ks=0; ks<BK/16; ks++){
            int kk = ks*16;
            // A fragments (2 m-tiles)
            unsigned af[2][4];
            #pragma unroll
            for (int i=0;i<2;i++){
                int am = wm*32 + i*16;
                af[i][0] = *(const unsigned*)(&As[am+g  ][kk + 2*tig    ]);
                af[i][1] = *(const unsigned*)(&As[am+g+8][kk + 2*tig    ]);
                af[i][2] = *(const unsigned*)(&As[am+g  ][kk + 2*tig + 8]);
                af[i][3] = *(const unsigned*)(&As[am+g+8][kk + 2*tig + 8]);
            }
            // B fragments (4 n-tiles)
            unsigned bf[4][2];
            #pragma unroll
            for (int j=0;j<4;j++){
                int bn = wn*32 + j*8;
                bf[j][0] = *(const unsigned*)(&Bs[bn+g][kk + 2*tig    ]);
                bf[j][1] = *(const unsigned*)(&Bs[bn+g][kk + 2*tig + 8]);
            }
            #pragma unroll
            for (int i=0;i<2;i++)
                #pragma unroll
                for (int j=0;j<4;j++){
                    asm volatile(
                        "mma.sync.aligned.m16n8k16.row.col.f32.bf16.bf16.f32 "
                        "{%0,%1,%2,%3}, {%4,%5,%6,%7}, {%8,%9}, {%0,%1,%2,%3};"
                        : "+f"(acc[i][j][0]), "+f"(acc[i][j][1]),
                          "+f"(acc[i][j][2]), "+f"(acc[i][j][3])
                        : "r"(af[i][0]), "r"(af[i][1]), "r"(af[i][2]), "r"(af[i][3]),
                          "r"(bf[j][0]), "r"(bf[j][1]));
                }
        }
        __syncthreads();
    }

    int* par = g_parent + b*Nq;
    const int* sl = g_selList + b*Nq;
    #pragma unroll
    for (int i=0;i<2;i++)
        #pragma unroll
        for (int j=0;j<4;j++)
            #pragma unroll
            for (int c=0;c<4;c++){
                int mi = r0 + wm*32 + i*16 + g + ((c>=2) ? 8 : 0);
                int mj = c0 + wn*32 + j*8 + 2*tig + (c & 1);
                if (mi < M && mj < M && acc[i][j][c] >= DUP_THR){
                    int ni = sl[mi], nj = sl[mj];
                    if (ni != nj) uf_union(par, ni, nj);
                }
            }
}

// flatten parents + per-component best
__global__ void k4_flatten(){
    int idx = blockIdx.x*256 + threadIdx.x;
    if (idx >= Bq*Nq) return;
    int b = idx / Nq, n = idx % Nq;
    int* par = g_parent + b*Nq;
    int r = uf_find(par, n);
    par[n] = r;
    if (g_sel[idx]){
        unsigned long long key = ((unsigned long long)__float_as_uint(g_score[idx]) << 32)
                               | (unsigned long long)(0xFFFFFFFFu - (unsigned)n);
        atomicMax(&g_best[b*Nq + r], key);
    }
}

// per-image exclusive scan over roots
__global__ void k5_scan(){
    int b = blockIdx.x;
    int t = threadIdx.x;                  // 1024
    const int IPT = (Nq + 1023)/1024;     // 6
    int base = t*IPT;
    int flags[IPT];
    int s = 0;
    #pragma unroll
    for (int i=0;i<IPT;i++){
        int n = base + i; int f = 0;
        if (n < Nq && g_sel[b*Nq+n] && g_parent[b*Nq+n] == n) f = 1;
        flags[i] = f; s += f;
    }
    int lane = t & 31, wid = t >> 5;
    int v = s;
    #pragma unroll
    for (int o=1;o<32;o<<=1){ int u=__shfl_up_sync(0xFFFFFFFFu,v,o); if(lane>=o) v+=u; }
    __shared__ int wsum[32];
    if (lane == 31) wsum[wid] = v;
    __syncthreads();
    if (wid == 0){
        int ww = wsum[lane];
        #pragma unroll
        for (int o=1;o<32;o<<=1){ int u=__shfl_up_sync(0xFFFFFFFFu,ww,o); if(lane>=o) ww+=u; }
        wsum[lane] = ww;
    }
    __syncthreads();
    int excl = v - s + (wid > 0 ? wsum[wid-1] : 0);
    if (t == 0) g_seedCount[b] = wsum[31];
    int p = excl;
    #pragma unroll
    for (int i=0;i<IPT;i++){
        if (flags[i]){
            int n = base + i;
            unsigned long long bk = g_best[b*Nq + n];
            int node = (int)(0xFFFFFFFFu - (unsigned)(bk & 0xFFFFFFFFull));
            g_slotNode[b*Nq + p] = node;
            p++;
        }
    }
}

// outputs: seed_signatures [B,N,C], pad_mask [B,N], seed_scores [B,N]
__global__ void k6_out(const float* __restrict__ qs, float* __restrict__ out){
    int row = blockIdx.x;                 // B*N blocks
    int b = row / Nq, slot = row % Nq;
    float v = 0.0f;
    bool valid = (slot < g_seedCount[b]);
    int node = valid ? g_slotNode[b*Nq + slot] : 0;
    if (valid){
        int l = node / Qq, q = node % Qq;
        v = qs[(((size_t)l*Bq + b)*Qq + q)*Cq + threadIdx.x];
    }
    out[(size_t)row*Cq + threadIdx.x] = v;
    if (threadIdx.x == 0){
        float* maskOut  = out + (size_t)Bq*Nq*Cq;
        float* scoreOut = maskOut + Bq*Nq;
        maskOut[row]  = valid ? 1.0f : 0.0f;
        scoreOut[row] = valid ? g_score[b*Nq + node] : 0.0f;
    }
}

// ---------------- launch ----------------
extern "C" void kernel_launch(void* const* d_in, const int* in_sizes, int n_in,
                              void* d_out, int out_size){
    const float* qs     = (const float*)d_in[0];  // [L,B,Q,C]
    const float* logits = (const float*)d_in[1];  // [L,B,Q]
    float* out = (float*)d_out;
    (void)in_sizes; (void)n_in; (void)out_size;

    k0_zero<<<1, 32>>>();
    k1_init<<<(Bq*Nq + 255)/256, 256>>>(logits);
    k2_normalize<<<Bq*Nq, 256>>>(qs);
    dim3 g3(NT, NT, Bq);
    k3_sim<<<g3, 128>>>();
    k4_flatten<<<(Bq*Nq + 255)/256, 256>>>();
    k5_scan<<<Bq, 1024>>>();
    k6_out<<<Bq*Nq, 256>>>(qs, out);
}

// round 3
// speedup vs baseline: 3.9305x; 1.1344x over previous
#include <cuda_runtime.h>
#include <cuda_bf16.h>
#include <math.h>

#define Bq 4
#define Lq 6
#define Qq 900
#define Cq 256
#define Nq (Lq*Qq)            /* 5400 */
#define BM2 128               /* block tile */
#define NT2 ((Nq+BM2-1)/BM2)  /* 43 */
#define TRI (NT2*(NT2+1)/2)   /* 946 triangular tiles */
#define BK 32
#define BKP 40                /* padded smem row (bf16) */
#define DUP_THR 0.8f

// ---------------- scratch (device globals) ----------------
__device__ __nv_bfloat16       g_normBf[(size_t)Bq*Nq*Cq];
__device__ int                 g_selList[Bq*Nq];
__device__ int                 g_parent[Bq*Nq];
__device__ unsigned long long  g_best[Bq*Nq];
__device__ unsigned char       g_sel[Bq*Nq];
__device__ float               g_score[Bq*Nq];
__device__ int                 g_slotNode[Bq*Nq];
__device__ int                 g_cnt[Bq];
__device__ int                 g_selCount[Bq];
__device__ int                 g_seedCount[Bq];
__device__ unsigned long long  g_argmax[Bq];

// ---------------- ptx helpers ----------------
__device__ __forceinline__ void cp16(void* sm, const void* g){
    unsigned sa = (unsigned)__cvta_generic_to_shared(sm);
    asm volatile("cp.async.cg.shared.global [%0], [%1], 16;\n" :: "r"(sa), "l"(g));
}
__device__ __forceinline__ void cp_commit(){
    asm volatile("cp.async.commit_group;\n");
}
template<int N> __device__ __forceinline__ void cp_wait(){
    asm volatile("cp.async.wait_group %0;\n" :: "n"(N));
}
__device__ __forceinline__ void ldsm4(unsigned &r0, unsigned &r1, unsigned &r2, unsigned &r3,
                                      const void* p){
    unsigned sa = (unsigned)__cvta_generic_to_shared(p);
    asm volatile("ldmatrix.sync.aligned.m8n8.x4.shared.b16 {%0,%1,%2,%3}, [%4];\n"
                 : "=r"(r0), "=r"(r1), "=r"(r2), "=r"(r3) : "r"(sa));
}

// ---------------- union-find ----------------
__device__ __forceinline__ int uf_find(int* parent, int x){
    while (true){
        int p = parent[x];
        if (p == x) return x;
        int gp = parent[p];
        if (gp != p){ parent[x] = gp; x = gp; }
        else return p;
    }
}
__device__ __forceinline__ void uf_union(int* parent, int a, int b){
    while (true){
        a = uf_find(parent, a);
        b = uf_find(parent, b);
        if (a == b) return;
        if (a > b){ int t=a; a=b; b=t; }
        if (atomicCAS(&parent[b], b, a) == b) return;
    }
}

// ---------------- kernels ----------------
__global__ void k0_zero(){
    int t = threadIdx.x;
    if (t < Bq){ g_cnt[t]=0; g_selCount[t]=0; g_seedCount[t]=0; g_argmax[t]=0ULL; }
}

__global__ void k1_init(const float* __restrict__ logits){
    int idx = blockIdx.x*256 + threadIdx.x;
    if (idx >= Bq*Nq) return;
    int b = idx / Nq, n = idx % Nq;
    int l = n / Qq, q = n % Qq;
    float lg = logits[(l*Bq + b)*Qq + q];
    float sc = 1.0f/(1.0f + expf(-lg));
    bool sel = (lg >= 0.0f);
    g_score[idx] = sc;
    g_sel[idx]   = sel ? 1 : 0;
    g_parent[idx]= n;
    g_best[idx]  = 0ULL;
    if (sel) atomicAdd(&g_cnt[b], 1);
    unsigned long long key = ((unsigned long long)__float_as_uint(sc) << 32)
                           | (unsigned long long)(0xFFFFFFFFu - (unsigned)n);
    atomicMax(&g_argmax[b], key);
}

// warp per row: selection decision, compaction, L2-normalize -> bf16 (vectorized)
__global__ void k2_normalize(const float* __restrict__ qs){
    int w    = threadIdx.x >> 5;
    int lane = threadIdx.x & 31;
    int row  = blockIdx.x*8 + w;                 // grid = B*N/8 = 2700
    if (row >= Bq*Nq) return;
    int b = row / Nq, n = row % Nq;
    int selEff = 0;
    if (lane == 0){
        if (g_cnt[b] > 0) selEff = (g_sel[row] != 0);
        else {
            unsigned am = 0xFFFFFFFFu - (unsigned)(g_argmax[b] & 0xFFFFFFFFull);
            selEff = ((unsigned)n == am);
        }
        g_sel[row] = (unsigned char)selEff;
    }
    selEff = __shfl_sync(0xFFFFFFFFu, selEff, 0);
    if (!selEff) return;
    int m = 0;
    if (lane == 0){
        m = atomicAdd(&g_selCount[b], 1);
        g_selList[b*Nq + m] = n;
    }
    m = __shfl_sync(0xFFFFFFFFu, m, 0);
    int l = n / Qq, q = n % Qq;
    const float4* src = (const float4*)(qs + (((size_t)l*Bq + b)*Qq + q)*Cq) + lane*2;
    float4 v0 = src[0], v1 = src[1];
    float s = v0.x*v0.x + v0.y*v0.y + v0.z*v0.z + v0.w*v0.w
            + v1.x*v1.x + v1.y*v1.y + v1.z*v1.z + v1.w*v1.w;
    #pragma unroll
    for (int o=16;o>0;o>>=1) s += __shfl_xor_sync(0xFFFFFFFFu, s, o);
    float r = rsqrtf(s + 1e-12f);
    __nv_bfloat162 h0 = __floats2bfloat162_rn(v0.x*r, v0.y*r);
    __nv_bfloat162 h1 = __floats2bfloat162_rn(v0.z*r, v0.w*r);
    __nv_bfloat162 h2 = __floats2bfloat162_rn(v1.x*r, v1.y*r);
    __nv_bfloat162 h3 = __floats2bfloat162_rn(v1.z*r, v1.w*r);
    uint4 pk;
    pk.x = *(unsigned*)&h0; pk.y = *(unsigned*)&h1;
    pk.z = *(unsigned*)&h2; pk.w = *(unsigned*)&h3;
    *((uint4*)(g_normBf + ((size_t)b*Nq + m)*Cq) + lane) = pk;
}

// bf16 tensor-core sim, 128x128 tile, cp.async double-buffered, ldmatrix frags
__global__ void __launch_bounds__(256, 2) k3_sim(){
    // triangular tile decode: by <= bx
    int t  = blockIdx.x;
    int bx = (int)((sqrtf(8.0f*(float)t + 1.0f) - 1.0f) * 0.5f);
    while ((bx+1)*(bx+2)/2 <= t) bx++;
    while (bx*(bx+1)/2 > t) bx--;
    int by = t - bx*(bx+1)/2;
    int b  = blockIdx.z;
    int M  = g_selCount[b];
    int r0 = by*BM2, c0 = bx*BM2;
    if (c0 >= M) return;                         // (r0 <= c0)

    __shared__ __nv_bfloat16 As[2][BM2][BKP];
    __shared__ __nv_bfloat16 Bs[2][BM2][BKP];

    const __nv_bfloat16* base = g_normBf + (size_t)b*Nq*Cq;
    int tid  = threadIdx.x;
    int lane = tid & 31;
    int w    = tid >> 5;                         // 0..7
    int wm   = w >> 1, wn = w & 1;               // 4x2 warp grid, warp tile 32x64
    int g    = lane >> 2;
    int tig  = lane & 3;

    // cp.async tile loader: 1024 x 16B chunks, 4 per thread
    auto load_stage = [&](int s, int k0){
        #pragma unroll
        for (int it=0; it<4; it++){
            int e  = tid + it*256;               // 0..1023
            int isB = e >> 9;
            int r  = (e & 511) >> 2;
            int ch = e & 3;
            int gr = isB ? (c0 + r) : (r0 + r);
            if (gr >= M) gr = 0;                 // epilogue guards discard junk
            const void* gp = base + (size_t)gr*Cq + k0 + ch*8;
            void* sp = isB ? (void*)&Bs[s][r][ch*8] : (void*)&As[s][r][ch*8];
            cp16(sp, gp);
        }
        cp_commit();
    };

    float acc[2][8][4];
    #pragma unroll
    for (int i=0;i<2;i++)
        #pragma unroll
        for (int j=0;j<8;j++)
            #pragma unroll
            for (int c=0;c<4;c++) acc[i][j][c] = 0.f;

    load_stage(0, 0);
    load_stage(1, BK);

    const int NKT = Cq/BK;                       // 8
    for (int kt=0; kt<NKT; kt++){
        cp_wait<1>();
        __syncthreads();
        int s = kt & 1;
        #pragma unroll
        for (int ks=0; ks<2; ks++){
            int kk = ks*16;
            unsigned af[2][4];
            #pragma unroll
            for (int i=0;i<2;i++){
                int am = wm*32 + i*16;
                ldsm4(af[i][0], af[i][1], af[i][2], af[i][3],
                      &As[s][am + (lane & 15)][kk + ((lane >> 4) << 3)]);
            }
            unsigned bf[8][2];
            #pragma unroll
            for (int jj=0; jj<4; jj++){
                int bn = wn*64 + jj*16;
                ldsm4(bf[2*jj][0], bf[2*jj][1], bf[2*jj+1][0], bf[2*jj+1][1],
                      &Bs[s][bn + ((lane & 7) | ((lane >> 4) << 3))]
                           [kk + (((lane >> 3) & 1) << 3)]);
            }
            #pragma unroll
            for (int i=0;i<2;i++)
                #pragma unroll
                for (int j=0;j<8;j++){
                    asm volatile(
                        "mma.sync.aligned.m16n8k16.row.col.f32.bf16.bf16.f32 "
                        "{%0,%1,%2,%3}, {%4,%5,%6,%7}, {%8,%9}, {%0,%1,%2,%3};"
                        : "+f"(acc[i][j][0]), "+f"(acc[i][j][1]),
                          "+f"(acc[i][j][2]), "+f"(acc[i][j][3])
                        : "r"(af[i][0]), "r"(af[i][1]), "r"(af[i][2]), "r"(af[i][3]),
                          "r"(bf[j][0]), "r"(bf[j][1]));
                }
        }
        __syncthreads();                         // all reads done before refill
        int knext = kt + 2;
        if (knext < NKT) load_stage(s, knext*BK);
        else cp_commit();                        // keep group counting aligned
    }

    int* par = g_parent + b*Nq;
    const int* sl = g_selList + b*Nq;
    #pragma unroll
    for (int i=0;i<2;i++)
        #pragma unroll
        for (int j=0;j<8;j++)
            #pragma unroll
            for (int c=0;c<4;c++){
                int mi = r0 + wm*32 + i*16 + g + ((c>=2) ? 8 : 0);
                int mj = c0 + wn*64 + j*8 + 2*tig + (c & 1);
                if (mi < M && mj < M && acc[i][j][c] >= DUP_THR){
                    int ni = sl[mi], nj = sl[mj];
                    if (ni != nj) uf_union(par, ni, nj);
                }
            }
}

// flatten parents + per-component best
__global__ void k4_flatten(){
    int idx = blockIdx.x*256 + threadIdx.x;
    if (idx >= Bq*Nq) return;
    int b = idx / Nq, n = idx % Nq;
    int* par = g_parent + b*Nq;
    int r = uf_find(par, n);
    par[n] = r;
    if (g_sel[idx]){
        unsigned long long key = ((unsigned long long)__float_as_uint(g_score[idx]) << 32)
                               | (unsigned long long)(0xFFFFFFFFu - (unsigned)n);
        atomicMax(&g_best[b*Nq + r], key);
    }
}

// per-image exclusive scan over roots
__global__ void k5_scan(){
    int b = blockIdx.x;
    int t = threadIdx.x;                  // 1024
    const int IPT = (Nq + 1023)/1024;     // 6
    int base = t*IPT;
    int flags[IPT];
    int s = 0;
    #pragma unroll
    for (int i=0;i<IPT;i++){
        int n = base + i; int f = 0;
        if (n < Nq && g_sel[b*Nq+n] && g_parent[b*Nq+n] == n) f = 1;
        flags[i] = f; s += f;
    }
    int lane = t & 31, wid = t >> 5;
    int v = s;
    #pragma unroll
    for (int o=1;o<32;o<<=1){ int u=__shfl_up_sync(0xFFFFFFFFu,v,o); if(lane>=o) v+=u; }
    __shared__ int wsum[32];
    if (lane == 31) wsum[wid] = v;
    __syncthreads();
    if (wid == 0){
        int ww = wsum[lane];
        #pragma unroll
        for (int o=1;o<32;o<<=1){ int u=__shfl_up_sync(0xFFFFFFFFu,ww,o); if(lane>=o) ww+=u; }
        wsum[lane] = ww;
    }
    __syncthreads();
    int excl = v - s + (wid > 0 ? wsum[wid-1] : 0);
    if (t == 0) g_seedCount[b] = wsum[31];
    int p = excl;
    #pragma unroll
    for (int i=0;i<IPT;i++){
        if (flags[i]){
            int n = base + i;
            unsigned long long bk = g_best[b*Nq + n];
            int node = (int)(0xFFFFFFFFu - (unsigned)(bk & 0xFFFFFFFFull));
            g_slotNode[b*Nq + p] = node;
            p++;
        }
    }
}

// warp per row outputs: seed_signatures [B,N,C] + pad_mask [B,N] + seed_scores [B,N]
__global__ void k6_out(const float* __restrict__ qs, float* __restrict__ out){
    int w    = threadIdx.x >> 5;
    int lane = threadIdx.x & 31;
    int row  = blockIdx.x*8 + w;                 // 2700 blocks
    if (row >= Bq*Nq) return;
    int b = row / Nq, slot = row % Nq;
    bool valid = (slot < g_seedCount[b]);
    int node = valid ? g_slotNode[b*Nq + slot] : 0;
    float4 o0 = make_float4(0,0,0,0), o1 = o0;
    if (valid){
        int l = node / Qq, q = node % Qq;
        const float4* src = (const float4*)(qs + (((size_t)l*Bq + b)*Qq + q)*Cq) + lane*2;
        o0 = src[0]; o1 = src[1];
    }
    float4* dst = (float4*)(out + (size_t)row*Cq) + lane*2;
    dst[0] = o0; dst[1] = o1;
    if (lane == 0){
        float* maskOut  = out + (size_t)Bq*Nq*Cq;
        float* scoreOut = maskOut + Bq*Nq;
        maskOut[row]  = valid ? 1.0f : 0.0f;
        scoreOut[row] = valid ? g_score[b*Nq + node] : 0.0f;
    }
}

// ---------------- launch ----------------
extern "C" void kernel_launch(void* const* d_in, const int* in_sizes, int n_in,
                              void* d_out, int out_size){
    const float* qs     = (const float*)d_in[0];  // [L,B,Q,C]
    const float* logits = (const float*)d_in[1];  // [L,B,Q]
    float* out = (float*)d_out;
    (void)in_sizes; (void)n_in; (void)out_size;

    k0_zero<<<1, 32>>>();
    k1_init<<<(Bq*Nq + 255)/256, 256>>>(logits);
    k2_normalize<<<(Bq*Nq + 7)/8, 256>>>(qs);
    dim3 g3(TRI, 1, Bq);
    k3_sim<<<g3, 256>>>();
    k4_flatten<<<(Bq*Nq + 255)/256, 256>>>();
    k5_scan<<<Bq, 1024>>>();
    k6_out<<<(Bq*Nq + 7)/8, 256>>>(qs, out);
}

// round 5
// speedup vs baseline: 4.4437x; 1.1306x over previous
#include <cuda_runtime.h>
#include <cuda_bf16.h>
#include <math.h>

#define Bq 4
#define Lq 6
#define Qq 900
#define Cq 256
#define Nq (Lq*Qq)            /* 5400 */
#define BM2 128
#define NT2 ((Nq+BM2-1)/BM2)  /* 43 */
#define TRI (NT2*(NT2+1)/2)   /* 946 */
#define BK 32
#define BKP 40
#define NSTG 3
#define DUP_THR 0.8f
#define DSMEM_BYTES (2*NSTG*BM2*BKP*2)  /* A+B, 3 stages, bf16 */

typedef unsigned long long ull;

// ---------------- scratch ----------------
__device__ __nv_bfloat16 g_normBf[(size_t)Bq*Nq*Cq];
__device__ int           g_selList[Bq*Nq];
__device__ int           g_parent[Bq*Nq];
__device__ ull           g_best[Bq*Nq];
__device__ unsigned char g_sel[Bq*Nq];
__device__ float         g_score[Bq*Nq];
__device__ int           g_slotNode[Bq*Nq];
__device__ int           g_selCount[Bq];
__device__ int           g_seedCount[Bq];

// ---------------- ptx helpers ----------------
__device__ __forceinline__ void cp16(void* smp, const void* g){
    unsigned sa = (unsigned)__cvta_generic_to_shared(smp);
    asm volatile("cp.async.cg.shared.global [%0], [%1], 16;\n" :: "r"(sa), "l"(g));
}
__device__ __forceinline__ void cp_commit(){ asm volatile("cp.async.commit_group;\n"); }
template<int N> __device__ __forceinline__ void cp_wait(){
    asm volatile("cp.async.wait_group %0;\n" :: "n"(N));
}
__device__ __forceinline__ void ldsm4(unsigned &r0, unsigned &r1, unsigned &r2, unsigned &r3,
                                      const void* p){
    unsigned sa = (unsigned)__cvta_generic_to_shared(p);
    asm volatile("ldmatrix.sync.aligned.m8n8.x4.shared.b16 {%0,%1,%2,%3}, [%4];\n"
                 : "=r"(r0), "=r"(r1), "=r"(r2), "=r"(r3) : "r"(sa));
}

// ---------------- union-find ----------------
__device__ __forceinline__ int uf_find(int* parent, int x){
    while (true){
        int p = parent[x];
        if (p == x) return x;
        int gp = parent[p];
        if (gp != p){ parent[x] = gp; x = gp; }
        else return p;
    }
}
__device__ __forceinline__ void uf_union(int* parent, int a, int b){
    while (true){
        a = uf_find(parent, a);
        b = uf_find(parent, b);
        if (a == b) return;
        if (a > b){ int t=a; a=b; b=t; }
        if (atomicCAS(&parent[b], b, a) == b) return;
    }
}

// ---------------- kInit: per-image scores/sel/argmax/compaction ----------------
__global__ void kInit(const float* __restrict__ logits){
    int b = blockIdx.x, t = threadIdx.x;       // 1024 threads
    const int IPT = 6;
    int base = t*IPT;
    float sc[IPT]; int sel[IPT];
    ull myMax = 0ULL; int myCnt = 0;
    #pragma unroll
    for (int i=0;i<IPT;i++){
        sc[i]=0.f; sel[i]=0;
        int n = base+i;
        if (n < Nq){
            int l = n/Qq, q = n%Qq;
            float lg = logits[(l*Bq+b)*Qq+q];
            float s = 1.f/(1.f+expf(-lg));
            sc[i]=s; sel[i] = (lg >= 0.f) ? 1 : 0;
            myCnt += sel[i];
            ull key = ((ull)__float_as_uint(s)<<32) | (ull)(0xFFFFFFFFu-(unsigned)n);
            if (key > myMax) myMax = key;
            int idx = b*Nq+n;
            g_score[idx] = s;
            g_parent[idx] = n;
            g_best[idx] = 0ULL;
        }
    }
    __shared__ int  redc[32];
    __shared__ ull  redm[32];
    __shared__ int  wsum[32];
    int lane = t & 31, wid = t >> 5;
    int c = myCnt; ull mx = myMax;
    #pragma unroll
    for (int o=16;o>0;o>>=1){
        c += __shfl_xor_sync(0xFFFFFFFFu, c, o);
        ull om = __shfl_xor_sync(0xFFFFFFFFu, mx, o);
        if (om > mx) mx = om;
    }
    if (lane == 0){ redc[wid]=c; redm[wid]=mx; }
    __syncthreads();
    if (wid == 0){
        c = redc[lane]; mx = redm[lane];
        #pragma unroll
        for (int o=16;o>0;o>>=1){
            c += __shfl_xor_sync(0xFFFFFFFFu, c, o);
            ull om = __shfl_xor_sync(0xFFFFFFFFu, mx, o);
            if (om > mx) mx = om;
        }
        if (lane == 0){ redc[0]=c; redm[0]=mx; }
    }
    __syncthreads();
    int cnt = redc[0]; ull bm = redm[0];
    if (cnt == 0){
        unsigned am = 0xFFFFFFFFu - (unsigned)(bm & 0xFFFFFFFFull);
        #pragma unroll
        for (int i=0;i<IPT;i++) sel[i] = ((unsigned)(base+i) == am) ? 1 : 0;
    }
    int s2 = 0;
    #pragma unroll
    for (int i=0;i<IPT;i++){
        int n = base+i;
        if (n < Nq) g_sel[b*Nq+n] = (unsigned char)sel[i];
        s2 += sel[i];
    }
    // block exclusive scan of s2
    int v = s2;
    #pragma unroll
    for (int o=1;o<32;o<<=1){ int u=__shfl_up_sync(0xFFFFFFFFu,v,o); if(lane>=o) v+=u; }
    if (lane == 31) wsum[wid] = v;
    __syncthreads();
    if (wid == 0){
        int ww = wsum[lane];
        #pragma unroll
        for (int o=1;o<32;o<<=1){ int u=__shfl_up_sync(0xFFFFFFFFu,ww,o); if(lane>=o) ww+=u; }
        wsum[lane] = ww;
    }
    __syncthreads();
    int excl = v - s2 + (wid > 0 ? wsum[wid-1] : 0);
    if (t == 0) g_selCount[b] = wsum[31];
    int p = excl;
    #pragma unroll
    for (int i=0;i<IPT;i++){
        if (sel[i]){ g_selList[b*Nq + p] = base+i; p++; }
    }
}

// ---------------- k2: warp per selected row, normalize -> bf16 ----------------
__global__ void k2_normalize(const float* __restrict__ qs){
    int w    = threadIdx.x >> 5;
    int lane = threadIdx.x & 31;
    int m    = blockIdx.x*8 + w;
    int b    = blockIdx.y;
    if (m >= g_selCount[b]) return;
    int n = g_selList[b*Nq + m];
    int l = n/Qq, q = n%Qq;
    const float4* src = (const float4*)(qs + (((size_t)l*Bq + b)*Qq + q)*Cq) + lane*2;
    float4 v0 = src[0], v1 = src[1];
    float s = v0.x*v0.x + v0.y*v0.y + v0.z*v0.z + v0.w*v0.w
            + v1.x*v1.x + v1.y*v1.y + v1.z*v1.z + v1.w*v1.w;
    #pragma unroll
    for (int o=16;o>0;o>>=1) s += __shfl_xor_sync(0xFFFFFFFFu, s, o);
    float r = rsqrtf(s + 1e-12f);
    __nv_bfloat162 h0 = __floats2bfloat162_rn(v0.x*r, v0.y*r);
    __nv_bfloat162 h1 = __floats2bfloat162_rn(v0.z*r, v0.w*r);
    __nv_bfloat162 h2 = __floats2bfloat162_rn(v1.x*r, v1.y*r);
    __nv_bfloat162 h3 = __floats2bfloat162_rn(v1.z*r, v1.w*r);
    uint4 pk;
    pk.x = *(unsigned*)&h0; pk.y = *(unsigned*)&h1;
    pk.z = *(unsigned*)&h2; pk.w = *(unsigned*)&h3;
    *((uint4*)(g_normBf + ((size_t)b*Nq + m)*Cq) + lane) = pk;
}

// ---------------- k3: bf16 HMMA sim, 3-stage cp.async pipeline ----------------
__global__ void __launch_bounds__(256, 2) k3_sim(){
    int t  = blockIdx.x;
    int bx = (int)((sqrtf(8.0f*(float)t + 1.0f) - 1.0f) * 0.5f);
    while ((bx+1)*(bx+2)/2 <= t) bx++;
    while (bx*(bx+1)/2 > t) bx--;
    int by = t - bx*(bx+1)/2;
    int b  = blockIdx.z;
    int M  = g_selCount[b];
    int r0 = by*BM2, c0 = bx*BM2;
    if (c0 >= M) return;
    bool diag = (bx == by);

    extern __shared__ __nv_bfloat16 sm[];
    __nv_bfloat16* Asb = sm;                       // [NSTG][BM2][BKP]
    __nv_bfloat16* Bsb = sm + NSTG*BM2*BKP;
    const __nv_bfloat16* Brd = diag ? Asb : Bsb;   // fragment source for B

    const __nv_bfloat16* base = g_normBf + (size_t)b*Nq*Cq;
    int tid  = threadIdx.x;
    int lane = tid & 31;
    int w    = tid >> 5;
    int wm   = w >> 1, wn = w & 1;
    int g    = lane >> 2;
    int tig  = lane & 3;

    auto load_stage = [&](int s, int k0){
        #pragma unroll
        for (int it=0; it<4; it++){
            if (diag && it >= 2) break;            // skip B tile on diagonal
            int e   = tid + it*256;                // 0..1023
            int isB = e >> 9;
            int r   = (e & 511) >> 2;
            int ch  = e & 3;
            int gr  = isB ? (c0 + r) : (r0 + r);
            if (gr >= M) gr = 0;
            const void* gp = base + (size_t)gr*Cq + k0 + ch*8;
            __nv_bfloat16* dstb = isB ? Bsb : Asb;
            void* sp = dstb + ((size_t)s*BM2 + r)*BKP + ch*8;
            cp16(sp, gp);
        }
        cp_commit();
    };

    float acc[2][8][4];
    #pragma unroll
    for (int i=0;i<2;i++)
        #pragma unroll
        for (int j=0;j<8;j++)
            #pragma unroll
            for (int c=0;c<4;c++) acc[i][j][c] = 0.f;

    load_stage(0, 0);
    load_stage(1, BK);

    const int NKT = Cq/BK;                         // 8
    for (int kt=0; kt<NKT; kt++){
        cp_wait<1>();
        __syncthreads();
        int knext = kt + 2;
        if (knext < NKT) load_stage(knext % NSTG, knext*BK);
        else cp_commit();                          // empty group keeps invariant
        int s = kt % NSTG;
        #pragma unroll
        for (int ks=0; ks<2; ks++){
            int kk = ks*16;
            unsigned af[2][4];
            #pragma unroll
            for (int i=0;i<2;i++){
                int am = wm*32 + i*16;
                ldsm4(af[i][0], af[i][1], af[i][2], af[i][3],
                      Asb + ((size_t)s*BM2 + am + (lane & 15))*BKP
                          + kk + ((lane >> 4) << 3));
            }
            unsigned bf[8][2];
            #pragma unroll
            for (int jj=0; jj<4; jj++){
                int bn = wn*64 + jj*16;
                ldsm4(bf[2*jj][0], bf[2*jj][1], bf[2*jj+1][0], bf[2*jj+1][1],
                      Brd + ((size_t)s*BM2 + bn + ((lane & 7) | ((lane >> 4) << 3)))*BKP
                          + kk + (((lane >> 3) & 1) << 3));
            }
            #pragma unroll
            for (int i=0;i<2;i++)
                #pragma unroll
                for (int j=0;j<8;j++){
                    asm volatile(
                        "mma.sync.aligned.m16n8k16.row.col.f32.bf16.bf16.f32 "
                        "{%0,%1,%2,%3}, {%4,%5,%6,%7}, {%8,%9}, {%0,%1,%2,%3};"
                        : "+f"(acc[i][j][0]), "+f"(acc[i][j][1]),
                          "+f"(acc[i][j][2]), "+f"(acc[i][j][3])
                        : "r"(af[i][0]), "r"(af[i][1]), "r"(af[i][2]), "r"(af[i][3]),
                          "r"(bf[j][0]), "r"(bf[j][1]));
                }
        }
    }

    int* par = g_parent + b*Nq;
    const int* sl = g_selList + b*Nq;
    #pragma unroll
    for (int i=0;i<2;i++)
        #pragma unroll
        for (int j=0;j<8;j++)
            #pragma unroll
            for (int c=0;c<4;c++){
                int mi = r0 + wm*32 + i*16 + g + ((c>=2) ? 8 : 0);
                int mj = c0 + wn*64 + j*8 + 2*tig + (c & 1);
                if (mi < M && mj < M && acc[i][j][c] >= DUP_THR){
                    int ni = sl[mi], nj = sl[mj];
                    if (ni != nj) uf_union(par, ni, nj);
                }
            }
}

// ---------------- k45: flatten + best + scan + mask/score outputs ----------------
__global__ void k45(float* __restrict__ out){
    int b = blockIdx.x, t = threadIdx.x;           // 1024 threads
    const int IPT = 6;
    int base = t*IPT;
    int* par = g_parent + b*Nq;
    int flags[IPT]; int s2 = 0;
    #pragma unroll
    for (int i=0;i<IPT;i++){
        flags[i] = 0;
        int n = base+i;
        if (n < Nq){
            int r = uf_find(par, n);
            par[n] = r;
            if (g_sel[b*Nq+n]){
                ull key = ((ull)__float_as_uint(g_score[b*Nq+n])<<32)
                        | (ull)(0xFFFFFFFFu-(unsigned)n);
                atomicMax(&g_best[b*Nq + r], key);
                if (r == n) flags[i] = 1;
            }
        }
        s2 += flags[i];
    }
    __syncthreads();                               // all best atomics visible
    __shared__ int wsum[32];
    int lane = t & 31, wid = t >> 5;
    int v = s2;
    #pragma unroll
    for (int o=1;o<32;o<<=1){ int u=__shfl_up_sync(0xFFFFFFFFu,v,o); if(lane>=o) v+=u; }
    if (lane == 31) wsum[wid] = v;
    __syncthreads();
    if (wid == 0){
        int ww = wsum[lane];
        #pragma unroll
        for (int o=1;o<32;o<<=1){ int u=__shfl_up_sync(0xFFFFFFFFu,ww,o); if(lane>=o) ww+=u; }
        wsum[lane] = ww;
    }
    __syncthreads();
    int excl = v - s2 + (wid > 0 ? wsum[wid-1] : 0);
    int K = wsum[31];
    if (t == 0) g_seedCount[b] = K;
    int p = excl;
    #pragma unroll
    for (int i=0;i<IPT;i++){
        if (flags[i]){
            int n = base+i;
            ull bk = g_best[b*Nq + n];
            int node = (int)(0xFFFFFFFFu - (unsigned)(bk & 0xFFFFFFFFull));
            g_slotNode[b*Nq + p] = node;
            p++;
        }
    }
    __syncthreads();                               // slotNode visible in block
    float* maskOut  = out + (size_t)Bq*Nq*Cq;
    float* scoreOut = maskOut + Bq*Nq;
    for (int n=t; n<Nq; n+=1024){
        bool valid = (n < K);
        int node = valid ? g_slotNode[b*Nq + n] : 0;
        maskOut[b*Nq+n]  = valid ? 1.0f : 0.0f;
        scoreOut[b*Nq+n] = valid ? g_score[b*Nq + node] : 0.0f;
    }
}

// ---------------- k6: seed_signatures [B,N,C] ----------------
__global__ void k6_out(const float* __restrict__ qs, float* __restrict__ out){
    int w    = threadIdx.x >> 5;
    int lane = threadIdx.x & 31;
    int slot = blockIdx.x*8 + w;
    int b    = blockIdx.y;
    if (slot >= Nq) return;
    bool valid = (slot < g_seedCount[b]);
    int node = valid ? g_slotNode[b*Nq + slot] : 0;
    float4 o0 = make_float4(0,0,0,0), o1 = o0;
    if (valid){
        int l = node/Qq, q = node%Qq;
        const float4* src = (const float4*)(qs + (((size_t)l*Bq + b)*Qq + q)*Cq) + lane*2;
        o0 = src[0]; o1 = src[1];
    }
    float4* dst = (float4*)(out + ((size_t)b*Nq + slot)*Cq) + lane*2;
    dst[0] = o0; dst[1] = o1;
}

// ---------------- launch ----------------
extern "C" void kernel_launch(void* const* d_in, const int* in_sizes, int n_in,
                              void* d_out, int out_size){
    const float* qs     = (const float*)d_in[0];
    const float* logits = (const float*)d_in[1];
    float* out = (float*)d_out;
    (void)in_sizes; (void)n_in; (void)out_size;

    cudaFuncSetAttribute(k3_sim, cudaFuncAttributeMaxDynamicSharedMemorySize, DSMEM_BYTES);

    kInit<<<Bq, 1024>>>(logits);
    dim3 g2((Nq + 7)/8, Bq);
    k2_normalize<<<g2, 256>>>(qs);
    dim3 g3(TRI, 1, Bq);
    k3_sim<<<g3, 256, DSMEM_BYTES>>>();
    k45<<<Bq, 1024>>>(out);
    k6_out<<<g2, 256>>>(qs, out);
}

// round 8
// speedup vs baseline: 4.4596x; 1.0036x over previous
#include <cuda_runtime.h>
#include <cuda_bf16.h>
#include <math.h>

#define Bq 4
#define Lq 6
#define Qq 900
#define Cq 256
#define Nq (Lq*Qq)            /* 5400 */
#define BM2 128
#define NT2 ((Nq+BM2-1)/BM2)  /* 43 */
#define TRI (NT2*(NT2+1)/2)   /* 946 */
#define BK 32
#define BKP 40
#define NSTG 4
#define DUP_THR 0.8f
#define DSMEM_BYTES (2*NSTG*BM2*BKP*2)  /* 81920 */

typedef unsigned long long ull;

// ---------------- scratch ----------------
__device__ __nv_bfloat16 g_normBf[(size_t)Bq*Nq*Cq];
__device__ int           g_selList[Bq*Nq];
__device__ int           g_parent[Bq*Nq];
__device__ ull           g_best[Bq*Nq];
__device__ unsigned char g_sel[Bq*Nq];
__device__ float         g_score[Bq*Nq];
__device__ int           g_slotNode[Bq*Nq];
__device__ int           g_selCount[Bq];
__device__ int           g_seedCount[Bq];

// ---------------- ptx helpers ----------------
__device__ __forceinline__ void cp16(void* smp, const void* g){
    unsigned sa = (unsigned)__cvta_generic_to_shared(smp);
    asm volatile("cp.async.cg.shared.global [%0], [%1], 16;\n" :: "r"(sa), "l"(g));
}
__device__ __forceinline__ void cp_commit(){ asm volatile("cp.async.commit_group;\n"); }
template<int N> __device__ __forceinline__ void cp_wait(){
    asm volatile("cp.async.wait_group %0;\n" :: "n"(N));
}
__device__ __forceinline__ void ldsm4(unsigned &r0, unsigned &r1, unsigned &r2, unsigned &r3,
                                      const void* p){
    unsigned sa = (unsigned)__cvta_generic_to_shared(p);
    asm volatile("ldmatrix.sync.aligned.m8n8.x4.shared.b16 {%0,%1,%2,%3}, [%4];\n"
                 : "=r"(r0), "=r"(r1), "=r"(r2), "=r"(r3) : "r"(sa));
}

// ---------------- union-find ----------------
__device__ __forceinline__ int uf_find(int* parent, int x){
    while (true){
        int p = parent[x];
        if (p == x) return x;
        int gp = parent[p];
        if (gp != p){ parent[x] = gp; x = gp; }
        else return p;
    }
}
__device__ __forceinline__ void uf_union(int* parent, int a, int b){
    while (true){
        a = uf_find(parent, a);
        b = uf_find(parent, b);
        if (a == b) return;
        if (a > b){ int t=a; a=b; b=t; }
        if (atomicCAS(&parent[b], b, a) == b) return;
    }
}

// ---------------- kInit: scores/sel/argmax-fallback/compaction ----------------
__global__ void kInit(const float* __restrict__ logits){
    int b = blockIdx.x, t = threadIdx.x;       // 1024 threads
    const int IPT = 6;
    int base = t*IPT;
    int sel[IPT];
    ull myMax = 0ULL; int myCnt = 0;
    #pragma unroll
    for (int i=0;i<IPT;i++){
        sel[i]=0;
        int n = base+i;
        if (n < Nq){
            int l = n/Qq, q = n%Qq;
            float lg = logits[(l*Bq+b)*Qq+q];
            float s = 1.f/(1.f+expf(-lg));
            sel[i] = (lg >= 0.f) ? 1 : 0;
            myCnt += sel[i];
            ull key = ((ull)__float_as_uint(s)<<32) | (ull)(0xFFFFFFFFu-(unsigned)n);
            if (key > myMax) myMax = key;
            int idx = b*Nq+n;
            g_score[idx] = s;
            g_parent[idx] = n;
            g_best[idx] = 0ULL;
        }
    }
    __shared__ int  redc[32];
    __shared__ ull  redm[32];
    __shared__ int  wsum[32];
    int lane = t & 31, wid = t >> 5;
    int c = myCnt; ull mx = myMax;
    #pragma unroll
    for (int o=16;o>0;o>>=1){
        c += __shfl_xor_sync(0xFFFFFFFFu, c, o);
        ull om = __shfl_xor_sync(0xFFFFFFFFu, mx, o);
        if (om > mx) mx = om;
    }
    if (lane == 0){ redc[wid]=c; redm[wid]=mx; }
    __syncthreads();
    if (wid == 0){
        c = redc[lane]; mx = redm[lane];
        #pragma unroll
        for (int o=16;o>0;o>>=1){
            c += __shfl_xor_sync(0xFFFFFFFFu, c, o);
            ull om = __shfl_xor_sync(0xFFFFFFFFu, mx, o);
            if (om > mx) mx = om;
        }
        if (lane == 0){ redc[0]=c; redm[0]=mx; }
    }
    __syncthreads();
    int cnt = redc[0]; ull bm = redm[0];
    if (cnt == 0){
        unsigned am = 0xFFFFFFFFu - (unsigned)(bm & 0xFFFFFFFFull);
        #pragma unroll
        for (int i=0;i<IPT;i++) sel[i] = ((unsigned)(base+i) == am) ? 1 : 0;
    }
    int s2 = 0;
    #pragma unroll
    for (int i=0;i<IPT;i++){
        int n = base+i;
        if (n < Nq) g_sel[b*Nq+n] = (unsigned char)sel[i];
        s2 += sel[i];
    }
    int v = s2;
    #pragma unroll
    for (int o=1;o<32;o<<=1){ int u=__shfl_up_sync(0xFFFFFFFFu,v,o); if(lane>=o) v+=u; }
    if (lane == 31) wsum[wid] = v;
    __syncthreads();
    if (wid == 0){
        int ww = wsum[lane];
        #pragma unroll
        for (int o=1;o<32;o<<=1){ int u=__shfl_up_sync(0xFFFFFFFFu,ww,o); if(lane>=o) ww+=u; }
        wsum[lane] = ww;
    }
    __syncthreads();
    int excl = v - s2 + (wid > 0 ? wsum[wid-1] : 0);
    if (t == 0) g_selCount[b] = wsum[31];
    int p = excl;
    #pragma unroll
    for (int i=0;i<IPT;i++){
        if (sel[i]){ g_selList[b*Nq + p] = base+i; p++; }
    }
}

// ---------------- k2: warp per selected row, normalize -> bf16 ----------------
__global__ void k2_normalize(const float* __restrict__ qs){
    int w    = threadIdx.x >> 5;
    int lane = threadIdx.x & 31;
    int m    = blockIdx.x*8 + w;
    int b    = blockIdx.y;
    if (m >= g_selCount[b]) return;
    int n = g_selList[b*Nq + m];
    int l = n/Qq, q = n%Qq;
    const float4* src = (const float4*)(qs + (((size_t)l*Bq + b)*Qq + q)*Cq) + lane*2;
    float4 v0 = src[0], v1 = src[1];
    float s = v0.x*v0.x + v0.y*v0.y + v0.z*v0.z + v0.w*v0.w
            + v1.x*v1.x + v1.y*v1.y + v1.z*v1.z + v1.w*v1.w;
    #pragma unroll
    for (int o=16;o>0;o>>=1) s += __shfl_xor_sync(0xFFFFFFFFu, s, o);
    float r = rsqrtf(s + 1e-12f);
    __nv_bfloat162 h0 = __floats2bfloat162_rn(v0.x*r, v0.y*r);
    __nv_bfloat162 h1 = __floats2bfloat162_rn(v0.z*r, v0.w*r);
    __nv_bfloat162 h2 = __floats2bfloat162_rn(v1.x*r, v1.y*r);
    __nv_bfloat162 h3 = __floats2bfloat162_rn(v1.z*r, v1.w*r);
    uint4 pk;
    pk.x = *(unsigned*)&h0; pk.y = *(unsigned*)&h1;
    pk.z = *(unsigned*)&h2; pk.w = *(unsigned*)&h3;
    *((uint4*)(g_normBf + ((size_t)b*Nq + m)*Cq) + lane) = pk;
}

// ---------------- k3: bf16 HMMA sim, 4-stage cp.async pipeline ----------------
__global__ void __launch_bounds__(256, 2) k3_sim(){
    int t  = blockIdx.x;
    int bx = (int)((sqrtf(8.0f*(float)t + 1.0f) - 1.0f) * 0.5f);
    while ((bx+1)*(bx+2)/2 <= t) bx++;
    while (bx*(bx+1)/2 > t) bx--;
    int by = t - bx*(bx+1)/2;
    int b  = blockIdx.z;
    int M  = g_selCount[b];
    int r0 = by*BM2, c0 = bx*BM2;
    if (c0 >= M) return;
    bool diag = (bx == by);

    extern __shared__ __nv_bfloat16 sm[];
    __nv_bfloat16* Asb = sm;                       // [NSTG][BM2][BKP]
    __nv_bfloat16* Bsb = sm + NSTG*BM2*BKP;
    const __nv_bfloat16* Brd = diag ? Asb : Bsb;

    const __nv_bfloat16* base = g_normBf + (size_t)b*Nq*Cq;
    int tid  = threadIdx.x;
    int lane = tid & 31;
    int w    = tid >> 5;
    int wm   = w >> 1, wn = w & 1;
    int g    = lane >> 2;
    int tig  = lane & 3;

    auto load_stage = [&](int s, int k0){
        #pragma unroll
        for (int it=0; it<4; it++){
            if (diag && it >= 2) break;            // skip B tile on diagonal
            int e   = tid + it*256;                // 0..1023
            int isB = e >> 9;
            int r   = (e & 511) >> 2;
            int ch  = e & 3;
            int gr  = isB ? (c0 + r) : (r0 + r);
            if (gr >= M) gr = 0;
            const void* gp = base + (size_t)gr*Cq + k0 + ch*8;
            __nv_bfloat16* dstb = isB ? Bsb : Asb;
            void* sp = dstb + ((size_t)s*BM2 + r)*BKP + ch*8;
            cp16(sp, gp);
        }
        cp_commit();
    };

    float acc[2][8][4];
    #pragma unroll
    for (int i=0;i<2;i++)
        #pragma unroll
        for (int j=0;j<8;j++)
            #pragma unroll
            for (int c=0;c<4;c++) acc[i][j][c] = 0.f;

    load_stage(0, 0);
    load_stage(1, BK);
    load_stage(2, 2*BK);

    const int NKT = Cq/BK;                         // 8
    for (int kt=0; kt<NKT; kt++){
        cp_wait<2>();                              // only group kt must be done
        __syncthreads();
        int knext = kt + 3;
        if (knext < NKT) load_stage(knext % NSTG, knext*BK);
        else cp_commit();                          // empty group keeps invariant
        int s = kt % NSTG;
        #pragma unroll
        for (int ks=0; ks<2; ks++){
            int kk = ks*16;
            unsigned af[2][4];
            #pragma unroll
            for (int i=0;i<2;i++){
                int am = wm*32 + i*16;
                ldsm4(af[i][0], af[i][1], af[i][2], af[i][3],
                      Asb + ((size_t)s*BM2 + am + (lane & 15))*BKP
                          + kk + ((lane >> 4) << 3));
            }
            unsigned bf[8][2];
            #pragma unroll
            for (int jj=0; jj<4; jj++){
                int bn = wn*64 + jj*16;
                ldsm4(bf[2*jj][0], bf[2*jj][1], bf[2*jj+1][0], bf[2*jj+1][1],
                      Brd + ((size_t)s*BM2 + bn + ((lane & 7) | ((lane >> 4) << 3)))*BKP
                          + kk + (((lane >> 3) & 1) << 3));
            }
            #pragma unroll
            for (int i=0;i<2;i++)
                #pragma unroll
                for (int j=0;j<8;j++){
                    asm volatile(
                        "mma.sync.aligned.m16n8k16.row.col.f32.bf16.bf16.f32 "
                        "{%0,%1,%2,%3}, {%4,%5,%6,%7}, {%8,%9}, {%0,%1,%2,%3};"
                        : "+f"(acc[i][j][0]), "+f"(acc[i][j][1]),
                          "+f"(acc[i][j][2]), "+f"(acc[i][j][3])
                        : "r"(af[i][0]), "r"(af[i][1]), "r"(af[i][2]), "r"(af[i][3]),
                          "r"(bf[j][0]), "r"(bf[j][1]));
                }
        }
    }

    int* par = g_parent + b*Nq;
    const int* sl = g_selList + b*Nq;
    #pragma unroll
    for (int i=0;i<2;i++)
        #pragma unroll
        for (int j=0;j<8;j++)
            #pragma unroll
            for (int c=0;c<4;c++){
                int mi = r0 + wm*32 + i*16 + g + ((c>=2) ? 8 : 0);
                int mj = c0 + wn*64 + j*8 + 2*tig + (c & 1);
                if (mi < M && mj < M && acc[i][j][c] >= DUP_THR){
                    int ni = sl[mi], nj = sl[mj];
                    if (ni != nj) uf_union(par, ni, nj);
                }
            }
}

// ---------------- k4: parallel flatten + per-component best ----------------
__global__ void k4_flatten(){
    int idx = blockIdx.x*256 + threadIdx.x;
    if (idx >= Bq*Nq) return;
    int b = idx / Nq, n = idx % Nq;
    int* par = g_parent + b*Nq;
    int r = uf_find(par, n);
    par[n] = r;
    if (g_sel[idx]){
        ull key = ((ull)__float_as_uint(g_score[idx])<<32)
                | (ull)(0xFFFFFFFFu-(unsigned)n);
        atomicMax(&g_best[b*Nq + r], key);
    }
}

// ---------------- k5: per-image scan + slotNode + mask/score ----------------
__global__ void k5_scan(float* __restrict__ out){
    int b = blockIdx.x, t = threadIdx.x;           // 1024 threads
    const int IPT = 6;
    int base = t*IPT;
    int flags[IPT]; int s2 = 0;
    #pragma unroll
    for (int i=0;i<IPT;i++){
        int n = base+i; flags[i] = 0;
        if (n < Nq && g_sel[b*Nq+n] && g_parent[b*Nq+n] == n) flags[i] = 1;
        s2 += flags[i];
    }
    __shared__ int wsum[32];
    int lane = t & 31, wid = t >> 5;
    int v = s2;
    #pragma unroll
    for (int o=1;o<32;o<<=1){ int u=__shfl_up_sync(0xFFFFFFFFu,v,o); if(lane>=o) v+=u; }
    if (lane == 31) wsum[wid] = v;
    __syncthreads();
    if (wid == 0){
        int ww = wsum[lane];
        #pragma unroll
        for (int o=1;o<32;o<<=1){ int u=__shfl_up_sync(0xFFFFFFFFu,ww,o); if(lane>=o) ww+=u; }
        wsum[lane] = ww;
    }
    __syncthreads();
    int excl = v - s2 + (wid > 0 ? wsum[wid-1] : 0);
    int K = wsum[31];
    if (t == 0) g_seedCount[b] = K;
    int p = excl;
    #pragma unroll
    for (int i=0;i<IPT;i++){
        if (flags[i]){
            int n = base+i;
            ull bk = g_best[b*Nq + n];
            int node = (int)(0xFFFFFFFFu - (unsigned)(bk & 0xFFFFFFFFull));
            g_slotNode[b*Nq + p] = node;
            p++;
        }
    }
    __syncthreads();
    float* maskOut  = out + (size_t)Bq*Nq*Cq;
    float* scoreOut = maskOut + Bq*Nq;
    for (int n=t; n<Nq; n+=1024){
        bool valid = (n < K);
        int node = valid ? g_slotNode[b*Nq + n] : 0;
        maskOut[b*Nq+n]  = valid ? 1.0f : 0.0f;
        scoreOut[b*Nq+n] = valid ? g_score[b*Nq + node] : 0.0f;
    }
}

// ---------------- k6: seed_signatures [B,N,C] ----------------
__global__ void k6_out(const float* __restrict__ qs, float* __restrict__ out){
    int w    = threadIdx.x >> 5;
    int lane = threadIdx.x & 31;
    int slot = blockIdx.x*8 + w;
    int b    = blockIdx.y;
    if (slot >= Nq) return;
    bool valid = (slot < g_seedCount[b]);
    int node = valid ? g_slotNode[b*Nq + slot] : 0;
    float4 o0 = make_float4(0,0,0,0), o1 = o0;
    if (valid){
        int l = node/Qq, q = node%Qq;
        const float4* src = (const float4*)(qs + (((size_t)l*Bq + b)*Qq + q)*Cq) + lane*2;
        o0 = src[0]; o1 = src[1];
    }
    float4* dst = (float4*)(out + ((size_t)b*Nq + slot)*Cq) + lane*2;
    dst[0] = o0; dst[1] = o1;
}

// ---------------- launch ----------------
extern "C" void kernel_launch(void* const* d_in, const int* in_sizes, int n_in,
                              void* d_out, int out_size){
    const float* qs     = (const float*)d_in[0];
    const float* logits = (const float*)d_in[1];
    float* out = (float*)d_out;
    (void)in_sizes; (void)n_in; (void)out_size;

    cudaFuncSetAttribute(k3_sim, cudaFuncAttributeMaxDynamicSharedMemorySize, DSMEM_BYTES);

    kInit<<<Bq, 1024>>>(logits);
    dim3 g2((Nq + 7)/8, Bq);
    k2_normalize<<<g2, 256>>>(qs);
    dim3 g3(TRI, 1, Bq);
    k3_sim<<<g3, 256, DSMEM_BYTES>>>();
    k4_flatten<<<(Bq*Nq + 255)/256, 256>>>();
    k5_scan<<<Bq, 1024>>>(out);
    k6_out<<<g2, 256>>>(qs, out);
}